// round 13
// baseline (speedup 1.0000x reference)
#include <cuda_runtime.h>
#include <math.h>

// Canny: blur+sobel fused (smem tiles) -> NMS -> hierarchical CCL -> output.
// Conv numerics: REVERSED row-major sequential FFMA (bit-match proven R10).

#define BATCH 16
#define H 1024
#define W 1024
#define NPIX (H * W)
#define TOT (BATCH * NPIX)

__device__ float         g_mag[TOT];
__device__ unsigned char g_dir[TOT];
__device__ unsigned char g_ws[TOT];       // bit0 = weak, bit1 = strong
__device__ int           g_label[TOT];    // union-find parent (weak only)
__device__ unsigned char g_rootflag[TOT]; // component-has-strong flag (by root)
__device__ int           g_maxi[BATCH];   // per-image max(mag) as int bits
__device__ float         g_w25[25];       // numpy-bit-exact gaussian weights

// ---------------------------------------------------------------------------
// K0: zero rootflag + maxi + (thread 0) numpy-bit-exact gaussian weights
__global__ void k_init() {
    int i = blockIdx.x * blockDim.x + threadIdx.x;
    if (i < TOT / 16) {
        reinterpret_cast<uint4*>(g_rootflag)[i] = make_uint4(0u, 0u, 0u, 0u);
    }
    if (i < BATCH) g_maxi[i] = 0;
    if (blockIdx.x == 0 && threadIdx.x == 0) {
        float gf[5];
#pragma unroll
        for (int t = 0; t < 5; t++) {
            double ax = (double)(t - 2);
            gf[t] = (float)exp(-0.5 * ax * ax);
        }
        float p[25];
#pragma unroll
        for (int r = 0; r < 5; r++)
#pragma unroll
            for (int c = 0; c < 5; c++)
                p[r * 5 + c] = __fmul_rn(gf[r], gf[c]);
        float acc8[8];
#pragma unroll
        for (int j = 0; j < 8; j++) acc8[j] = p[j];
#pragma unroll
        for (int j = 0; j < 8; j++) acc8[j] = __fadd_rn(acc8[j], p[8 + j]);
#pragma unroll
        for (int j = 0; j < 8; j++) acc8[j] = __fadd_rn(acc8[j], p[16 + j]);
        float s01 = __fadd_rn(acc8[0], acc8[1]);
        float s23 = __fadd_rn(acc8[2], acc8[3]);
        float s45 = __fadd_rn(acc8[4], acc8[5]);
        float s67 = __fadd_rn(acc8[6], acc8[7]);
        float res = __fadd_rn(__fadd_rn(s01, s23), __fadd_rn(s45, s67));
        res = __fadd_rn(res, p[24]);
#pragma unroll
        for (int k = 0; k < 25; k++) g_w25[k] = __fdiv_rn(p[k], res);
    }
}

// ---------------------------------------------------------------------------
__device__ __forceinline__ unsigned char direction_of(float gx, float gy) {
    float deg = __fmul_rn(atan2f(gy, gx), 57.29577951308232f);
    float r = fmodf(deg, 180.0f);
    if (r < 0.0f) r = __fadd_rn(r, 180.0f);

    float d0 = fabsf(r - 22.5f);
    float d1 = fabsf(r - 67.5f);
    float d2 = fabsf(r - 112.5f);
    float d3 = fabsf(r - 157.5f);
    float dmin = fminf(fminf(d0, d1), fminf(d2, d3));
    if (dmin < 2e-4f) {
        float at = (float)atan2((double)gy, (double)gx);
        deg = __fmul_rn(at, 57.29577951308232f);
        r = fmodf(deg, 180.0f);
        if (r < 0.0f) r = __fadd_rn(r, 180.0f);
    }

    if (r < 22.5f || r >= 157.5f) return 0;
    else if (r < 67.5f)           return 1;
    else if (r < 112.5f)          return 2;
    else                          return 3;
}

// ---------------------------------------------------------------------------
// K1: fused blur+sobel+mag/dir + per-image max (one atomic per block)
// Tile 32x16 pixels. Input halo 3, blur halo 1 (zeroed outside image = the
// reference's zero padding of the blurred tensor before sobel).
#define TX 32
#define TY 16
#define INW (TX + 6)   // 38
#define INH (TY + 6)   // 22
#define BLW (TX + 2)   // 34
#define BLH (TY + 2)   // 18

__global__ __launch_bounds__(512) void k_blursobel(const float* __restrict__ xin) {
    __shared__ float s_in[INH][INW + 2];    // pad
    __shared__ float s_bl[BLH][BLW + 2];
    __shared__ float s_red[16];

    int tx = threadIdx.x, ty = threadIdx.y;
    int tid = ty * TX + tx;
    int bx0 = blockIdx.x * TX, by0 = blockIdx.y * TY;
    int b = blockIdx.z;
    const float* __restrict__ img = xin + ((size_t)b * 3 + 1) * NPIX;

    // load input tile + halo 3 (zero outside image)
    for (int j = tid; j < INW * INH; j += 512) {
        int r = j / INW, c = j % INW;
        int gx = bx0 - 3 + c, gy = by0 - 3 + r;
        s_in[r][c] = (gx >= 0 && gx < W && gy >= 0 && gy < H) ? __ldg(img + gy * W + gx) : 0.0f;
    }

    float w[25];
#pragma unroll
    for (int k = 0; k < 25; k++) w[k] = g_w25[k];
    __syncthreads();

    // blur for tile + halo 1 (REVERSED row-major FFMA; 0 outside image)
    for (int j = tid; j < BLW * BLH; j += 512) {
        int r = j / BLW, c = j % BLW;
        int px = bx0 - 1 + c, py = by0 - 1 + r;
        float acc = 0.0f;
        if (px >= 0 && px < W && py >= 0 && py < H) {
#pragma unroll
            for (int ky = 4; ky >= 0; ky--) {
#pragma unroll
                for (int kx = 4; kx >= 0; kx--) {
                    acc = __fmaf_rn(w[ky * 5 + kx], s_in[r + ky][c + kx], acc);
                }
            }
        }
        s_bl[r][c] = acc;
    }
    __syncthreads();

    // sobel at (tx,ty): blur rel coords (ty+i, tx+j)
    float a[3][3];
#pragma unroll
    for (int i = 0; i < 3; i++)
#pragma unroll
        for (int j = 0; j < 3; j++)
            a[i][j] = s_bl[ty + i][tx + j];

    float gx = 0.0f;
    gx = __fmaf_rn( 1.0f, a[2][2], gx);
    gx = __fmaf_rn(-1.0f, a[2][0], gx);
    gx = __fmaf_rn( 2.0f, a[1][2], gx);
    gx = __fmaf_rn(-2.0f, a[1][0], gx);
    gx = __fmaf_rn( 1.0f, a[0][2], gx);
    gx = __fmaf_rn(-1.0f, a[0][0], gx);

    float gy = 0.0f;
    gy = __fmaf_rn( 1.0f, a[2][2], gy);
    gy = __fmaf_rn( 2.0f, a[2][1], gy);
    gy = __fmaf_rn( 1.0f, a[2][0], gy);
    gy = __fmaf_rn(-1.0f, a[0][2], gy);
    gy = __fmaf_rn(-2.0f, a[0][1], gy);
    gy = __fmaf_rn(-1.0f, a[0][0], gy);

    float m2  = __fadd_rn(__fadd_rn(__fmul_rn(gx, gx), __fmul_rn(gy, gy)), 1e-12f);
    float mag = __fsqrt_rn(m2);

    size_t idx = (size_t)b * NPIX + (size_t)(by0 + ty) * W + (bx0 + tx);
    g_mag[idx] = mag;
    g_dir[idx] = direction_of(gx, gy);

    // block max (warp shuffle + smem), one atomicMax(int) per block
    float m = mag;
#pragma unroll
    for (int s = 16; s > 0; s >>= 1)
        m = fmaxf(m, __shfl_xor_sync(0xFFFFFFFFu, m, s));
    if ((tid & 31) == 0) s_red[tid >> 5] = m;
    __syncthreads();
    if (tid < 16) {
        m = s_red[tid];
#pragma unroll
        for (int s = 8; s > 0; s >>= 1)
            m = fmaxf(m, __shfl_xor_sync(0xFFFFu, m, s));
        if (tid == 0) atomicMax(&g_maxi[b], __float_as_int(m));
    }
}

// ---------------------------------------------------------------------------
// K2: NMS + double threshold
__global__ __launch_bounds__(256) void k_nms(const float* __restrict__ lowp,
                                             const float* __restrict__ highp) {
    int x = blockIdx.x * 32 + threadIdx.x;
    int y = blockIdx.y * 8 + threadIdx.y;
    int b = blockIdx.z;
    const float* __restrict__ mg = g_mag + (size_t)b * NPIX;

    float denom = __fadd_rn(__int_as_float(g_maxi[b]), 1e-12f);
    float low  = __ldg(lowp);
    float high = __ldg(highp);

    size_t idx = (size_t)b * NPIX + y * W + x;
    float m = mg[y * W + x];
    int   d = g_dir[idx];

    auto nb = [&](int yy, int xx) -> float {
        return (yy >= 0 && yy < H && xx >= 0 && xx < W) ? mg[yy * W + xx] : 0.0f;
    };

    float n1, n2;
    if (d == 0)      { n1 = nb(y,     x + 1); n2 = nb(y,     x - 1); }
    else if (d == 1) { n1 = nb(y - 1, x + 1); n2 = nb(y + 1, x - 1); }
    else if (d == 2) { n1 = nb(y - 1, x);     n2 = nb(y + 1, x);     }
    else             { n1 = nb(y - 1, x - 1); n2 = nb(y + 1, x + 1); }

    float mn  = __fdiv_rn(m,  denom);
    float n1n = __fdiv_rn(n1, denom);
    float n2n = __fdiv_rn(n2, denom);
    float nms = (mn >= n1n && mn >= n2n) ? mn : 0.0f;

    unsigned char ws = 0;
    if (nms >= low)  ws |= 1;
    if (nms >= high) ws |= 2;

    g_ws[idx] = ws;
}

// ---------------------------------------------------------------------------
// Shared-memory union-find (tile-local, min-root)
__device__ __forceinline__ int lfind(int* lp, int i) {
    volatile int* L = lp;
    while (true) {
        int p = L[i];
        if (p == i) return i;
        int gp = L[p];
        if (gp == p) return p;
        lp[i] = gp;
        i = gp;
    }
}
__device__ __forceinline__ void lunion(int* lp, int a, int b) {
    while (true) {
        a = lfind(lp, a);
        b = lfind(lp, b);
        if (a == b) return;
        if (a > b) { int t = a; a = b; b = t; }
        int old = atomicCAS(&lp[b], b, a);
        if (old == b) return;
        b = old;
    }
}

// Global union-find (min-root)
__device__ __forceinline__ int uf_find(int i) {
    volatile int* L = g_label;
    while (true) {
        int p = L[i];
        if (p == i) return i;
        int gp = L[p];
        if (gp == p) return p;
        g_label[i] = gp;
        i = gp;
    }
}
__device__ __forceinline__ int uf_find_ro(int i) {
    volatile int* L = g_label;
    while (true) {
        int p = L[i];
        if (p == i) return i;
        i = p;
    }
}
__device__ __forceinline__ void uf_union(int a, int b) {
    while (true) {
        a = uf_find(a);
        b = uf_find(b);
        if (a == b) return;
        if (a > b) { int t = a; a = b; b = t; }
        int old = atomicCAS(&g_label[b], b, a);
        if (old == b) return;
        b = old;
    }
}

// ---------------------------------------------------------------------------
// K3: tile-local CCL (32x32 tile, smem UF, ws staged in smem)
__global__ __launch_bounds__(1024) void k_local() {
    __shared__ int lp[1024];
    __shared__ unsigned char lws[1024];
    int lx = threadIdx.x, ly = threadIdx.y;
    int l  = ly * 32 + lx;
    int x  = blockIdx.x * 32 + lx;
    int y  = blockIdx.y * 32 + ly;
    int b  = blockIdx.z;
    int gi = b * NPIX + y * W + x;

    unsigned char wsv = g_ws[gi];
    lws[l] = wsv;
    lp[l] = l;
    __syncthreads();

    bool w = (wsv & 1);
    if (w) {
        if (lx < 31 && (lws[l + 1] & 1)) lunion(lp, l, l + 1);
        if (ly < 31) {
            if (           (lws[l + 32] & 1)) lunion(lp, l, l + 32);
            if (lx > 0  && (lws[l + 31] & 1)) lunion(lp, l, l + 31);
            if (lx < 31 && (lws[l + 33] & 1)) lunion(lp, l, l + 33);
        }
    }
    __syncthreads();

    if (w) {
        int r  = lfind(lp, l);
        int rx = r & 31, ry = r >> 5;
        g_label[gi] = b * NPIX + (blockIdx.y * 32 + ry) * W + (blockIdx.x * 32 + rx);
    }
}

// ---------------------------------------------------------------------------
// K4: merge weak pairs crossing 32x32 tile boundaries
__global__ __launch_bounds__(256) void k_border() {
    int i = blockIdx.x * blockDim.x + threadIdx.x;
    if (i >= TOT) return;
    if (!(g_ws[i] & 1)) return;

    int pi = i % NPIX;
    int x  = pi % W;
    int y  = pi / W;

    bool xe = ((x & 31) == 31);
    bool x0 = ((x & 31) == 0);
    bool ye = ((y & 31) == 31);

    if (x < W - 1 && xe && (g_ws[i + 1] & 1)) uf_union(i, i + 1);
    if (y < H - 1) {
        if (ye                       && (g_ws[i + W]     & 1)) uf_union(i, i + W);
        if (x > 0     && (ye || x0)  && (g_ws[i + W - 1] & 1)) uf_union(i, i + W - 1);
        if (x < W - 1 && (ye || xe)  && (g_ws[i + W + 1] & 1)) uf_union(i, i + W + 1);
    }
}

// ---------------------------------------------------------------------------
// K5: flatten weak labels (find from tile root) + mark strong components
__global__ __launch_bounds__(256) void k_flatmark() {
    int i = blockIdx.x * blockDim.x + threadIdx.x;
    if (i >= TOT) return;
    unsigned char ws = g_ws[i];
    if (ws & 1) {
        int r = uf_find_ro(g_label[i]);
        g_label[i] = r;
        if (ws & 2) g_rootflag[r] = 1;
    }
}

// ---------------------------------------------------------------------------
// K6: output = 50 * (edge - threshold)
__global__ __launch_bounds__(256) void k_out(float* __restrict__ out,
                                             const float* __restrict__ thrp) {
    int i = blockIdx.x * blockDim.x + threadIdx.x;
    if (i >= TOT) return;
    float thr = __ldg(thrp);
    float e = 0.0f;
    if (g_ws[i] & 1) {
        if (g_rootflag[g_label[i]]) e = 1.0f;
    }
    out[i] = __fmul_rn(50.0f, __fadd_rn(e, -thr));
}

// ---------------------------------------------------------------------------
extern "C" void kernel_launch(void* const* d_in, const int* in_sizes, int n_in,
                              void* d_out, int out_size) {
    const float* x     = (const float*)d_in[0];
    const float* thr   = (const float*)d_in[1];
    const float* low   = (const float*)d_in[2];
    const float* high  = (const float*)d_in[3];
    float*       out   = (float*)d_out;

    dim3 blkF(32, 16);
    dim3 grdF(W / 32, H / 16, BATCH);   // fused blur+sobel
    dim3 blkN(32, 8);
    dim3 grdN(W / 32, H / 8, BATCH);    // nms
    dim3 blk32(32, 32);
    dim3 grd32(W / 32, H / 32, BATCH);  // local CCL

    k_init<<<(TOT / 16 + 255) / 256, 256>>>();
    k_blursobel<<<grdF, blkF>>>(x);
    k_nms<<<grdN, blkN>>>(low, high);
    k_local<<<grd32, blk32>>>();
    k_border<<<(TOT + 255) / 256, 256>>>();
    k_flatmark<<<(TOT + 255) / 256, 256>>>();
    k_out<<<(TOT + 255) / 256, 256>>>(out, thr);
}

// round 14
// speedup vs baseline: 1.2487x; 1.2487x over previous
#include <cuda_runtime.h>
#include <math.h>

// Canny: blur -> sobel(+max) -> NMS -> hierarchical CCL (ballot-run local UF,
// border merge, flatten/mark) -> output.
// Conv numerics: REVERSED row-major sequential FFMA (bit-match proven R10).

#define BATCH 16
#define H 1024
#define W 1024
#define NPIX (H * W)
#define TOT (BATCH * NPIX)

__device__ float         g_blur[TOT];
__device__ float         g_mag[TOT];
__device__ unsigned char g_dir[TOT];
__device__ unsigned char g_ws[TOT];       // bit0 = weak, bit1 = strong
__device__ int           g_label[TOT];    // union-find parent (weak only)
__device__ unsigned char g_rootflag[TOT]; // component-has-strong flag (by root)
__device__ int           g_maxi[BATCH];   // per-image max(mag) as int bits
__device__ float         g_w25[25];       // numpy-bit-exact gaussian weights

// ---------------------------------------------------------------------------
// K0: zero rootflag + maxi + (thread 0) numpy-bit-exact gaussian weights
__global__ void k_init() {
    int i = blockIdx.x * blockDim.x + threadIdx.x;
    if (i < TOT / 16) {
        reinterpret_cast<uint4*>(g_rootflag)[i] = make_uint4(0u, 0u, 0u, 0u);
    }
    if (i < BATCH) g_maxi[i] = 0;
    if (blockIdx.x == 0 && threadIdx.x == 0) {
        float gf[5];
#pragma unroll
        for (int t = 0; t < 5; t++) {
            double ax = (double)(t - 2);
            gf[t] = (float)exp(-0.5 * ax * ax);
        }
        float p[25];
#pragma unroll
        for (int r = 0; r < 5; r++)
#pragma unroll
            for (int c = 0; c < 5; c++)
                p[r * 5 + c] = __fmul_rn(gf[r], gf[c]);
        float acc8[8];
#pragma unroll
        for (int j = 0; j < 8; j++) acc8[j] = p[j];
#pragma unroll
        for (int j = 0; j < 8; j++) acc8[j] = __fadd_rn(acc8[j], p[8 + j]);
#pragma unroll
        for (int j = 0; j < 8; j++) acc8[j] = __fadd_rn(acc8[j], p[16 + j]);
        float s01 = __fadd_rn(acc8[0], acc8[1]);
        float s23 = __fadd_rn(acc8[2], acc8[3]);
        float s45 = __fadd_rn(acc8[4], acc8[5]);
        float s67 = __fadd_rn(acc8[6], acc8[7]);
        float res = __fadd_rn(__fadd_rn(s01, s23), __fadd_rn(s45, s67));
        res = __fadd_rn(res, p[24]);
#pragma unroll
        for (int k = 0; k < 25; k++) g_w25[k] = __fdiv_rn(p[k], res);
    }
}

// ---------------------------------------------------------------------------
// K1: 5x5 Gaussian blur, REVERSED row-major FFMA (bit-matches reference)
__global__ __launch_bounds__(256) void k_blur(const float* __restrict__ x) {
    int px = blockIdx.x * 32 + threadIdx.x;
    int py = blockIdx.y * 8 + threadIdx.y;
    int b  = blockIdx.z;
    const float* __restrict__ img = x + ((size_t)b * 3 + 1) * NPIX;

    float w[25];
#pragma unroll
    for (int k = 0; k < 25; k++) w[k] = g_w25[k];

    float acc = 0.0f;
#pragma unroll
    for (int ky = 4; ky >= 0; ky--) {
        int sy = py + ky - 2;
        bool yok = (sy >= 0 && sy < H);
#pragma unroll
        for (int kx = 4; kx >= 0; kx--) {
            int sx = px + kx - 2;
            float v = (yok && sx >= 0 && sx < W) ? __ldg(img + sy * W + sx) : 0.0f;
            acc = __fmaf_rn(w[ky * 5 + kx], v, acc);
        }
    }
    g_blur[(size_t)b * NPIX + py * W + px] = acc;
}

// ---------------------------------------------------------------------------
__device__ __forceinline__ unsigned char direction_of(float gx, float gy) {
    float deg = __fmul_rn(atan2f(gy, gx), 57.29577951308232f);
    float r = fmodf(deg, 180.0f);
    if (r < 0.0f) r = __fadd_rn(r, 180.0f);

    float d0 = fabsf(r - 22.5f);
    float d1 = fabsf(r - 67.5f);
    float d2 = fabsf(r - 112.5f);
    float d3 = fabsf(r - 157.5f);
    float dmin = fminf(fminf(d0, d1), fminf(d2, d3));
    if (dmin < 2e-4f) {
        float at = (float)atan2((double)gy, (double)gx);
        deg = __fmul_rn(at, 57.29577951308232f);
        r = fmodf(deg, 180.0f);
        if (r < 0.0f) r = __fadd_rn(r, 180.0f);
    }

    if (r < 22.5f || r >= 157.5f) return 0;
    else if (r < 67.5f)           return 1;
    else if (r < 112.5f)          return 2;
    else                          return 3;
}

// ---------------------------------------------------------------------------
// K2: Sobel (reversed row-major FFMA) -> mag/dir + per-image max (1 atomic/blk)
__global__ __launch_bounds__(256) void k_sobel() {
    int x = blockIdx.x * 32 + threadIdx.x;
    int y = blockIdx.y * 8 + threadIdx.y;
    int b = blockIdx.z;
    const float* __restrict__ img = g_blur + (size_t)b * NPIX;

    float a[3][3];
#pragma unroll
    for (int i = 0; i < 3; i++) {
#pragma unroll
        for (int j = 0; j < 3; j++) {
            int yy = y + i - 1, xx = x + j - 1;
            a[i][j] = (yy >= 0 && yy < H && xx >= 0 && xx < W) ? img[yy * W + xx] : 0.0f;
        }
    }
    float gx = 0.0f;
    gx = __fmaf_rn( 1.0f, a[2][2], gx);
    gx = __fmaf_rn(-1.0f, a[2][0], gx);
    gx = __fmaf_rn( 2.0f, a[1][2], gx);
    gx = __fmaf_rn(-2.0f, a[1][0], gx);
    gx = __fmaf_rn( 1.0f, a[0][2], gx);
    gx = __fmaf_rn(-1.0f, a[0][0], gx);

    float gy = 0.0f;
    gy = __fmaf_rn( 1.0f, a[2][2], gy);
    gy = __fmaf_rn( 2.0f, a[2][1], gy);
    gy = __fmaf_rn( 1.0f, a[2][0], gy);
    gy = __fmaf_rn(-1.0f, a[0][2], gy);
    gy = __fmaf_rn(-2.0f, a[0][1], gy);
    gy = __fmaf_rn(-1.0f, a[0][0], gy);

    float m2  = __fadd_rn(__fadd_rn(__fmul_rn(gx, gx), __fmul_rn(gy, gy)), 1e-12f);
    float mag = __fsqrt_rn(m2);

    size_t idx = (size_t)b * NPIX + y * W + x;
    g_mag[idx] = mag;
    g_dir[idx] = direction_of(gx, gy);

    // per-block max via warp shuffles, one atomicMax(int) per block (exact:
    // int compare == float compare for non-negative floats)
    __shared__ float s_red[8];
    int t = threadIdx.y * 32 + threadIdx.x;
    float m = mag;
#pragma unroll
    for (int s = 16; s > 0; s >>= 1)
        m = fmaxf(m, __shfl_xor_sync(0xFFFFFFFFu, m, s));
    if ((t & 31) == 0) s_red[t >> 5] = m;
    __syncthreads();
    if (t < 8) {
        m = s_red[t];
#pragma unroll
        for (int s = 4; s > 0; s >>= 1)
            m = fmaxf(m, __shfl_xor_sync(0xFFu, m, s));
        if (t == 0) atomicMax(&g_maxi[b], __float_as_int(m));
    }
}

// ---------------------------------------------------------------------------
// K3: NMS + double threshold
__global__ __launch_bounds__(256) void k_nms(const float* __restrict__ lowp,
                                             const float* __restrict__ highp) {
    int x = blockIdx.x * 32 + threadIdx.x;
    int y = blockIdx.y * 8 + threadIdx.y;
    int b = blockIdx.z;
    const float* __restrict__ mg = g_mag + (size_t)b * NPIX;

    float denom = __fadd_rn(__int_as_float(g_maxi[b]), 1e-12f);
    float low  = __ldg(lowp);
    float high = __ldg(highp);

    size_t idx = (size_t)b * NPIX + y * W + x;
    float m = mg[y * W + x];
    int   d = g_dir[idx];

    auto nb = [&](int yy, int xx) -> float {
        return (yy >= 0 && yy < H && xx >= 0 && xx < W) ? mg[yy * W + xx] : 0.0f;
    };

    float n1, n2;
    if (d == 0)      { n1 = nb(y,     x + 1); n2 = nb(y,     x - 1); }
    else if (d == 1) { n1 = nb(y - 1, x + 1); n2 = nb(y + 1, x - 1); }
    else if (d == 2) { n1 = nb(y - 1, x);     n2 = nb(y + 1, x);     }
    else             { n1 = nb(y - 1, x - 1); n2 = nb(y + 1, x + 1); }

    float mn  = __fdiv_rn(m,  denom);
    float n1n = __fdiv_rn(n1, denom);
    float n2n = __fdiv_rn(n2, denom);
    float nms = (mn >= n1n && mn >= n2n) ? mn : 0.0f;

    unsigned char ws = 0;
    if (nms >= low)  ws |= 1;
    if (nms >= high) ws |= 2;

    g_ws[idx] = ws;
}

// ---------------------------------------------------------------------------
// Shared-memory union-find (tile-local, min-root)
__device__ __forceinline__ int lfind(int* lp, int i) {
    volatile int* L = lp;
    while (true) {
        int p = L[i];
        if (p == i) return i;
        int gp = L[p];
        if (gp == p) return p;
        lp[i] = gp;
        i = gp;
    }
}
__device__ __forceinline__ void lunion(int* lp, int a, int b) {
    while (true) {
        a = lfind(lp, a);
        b = lfind(lp, b);
        if (a == b) return;
        if (a > b) { int t = a; a = b; b = t; }
        int old = atomicCAS(&lp[b], b, a);
        if (old == b) return;
        b = old;
    }
}

// Global union-find (min-root)
__device__ __forceinline__ int uf_find(int i) {
    volatile int* L = g_label;
    while (true) {
        int p = L[i];
        if (p == i) return i;
        int gp = L[p];
        if (gp == p) return p;
        g_label[i] = gp;
        i = gp;
    }
}
__device__ __forceinline__ int uf_find_ro(int i) {
    volatile int* L = g_label;
    while (true) {
        int p = L[i];
        if (p == i) return i;
        i = p;
    }
}
__device__ __forceinline__ void uf_union(int a, int b) {
    while (true) {
        a = uf_find(a);
        b = uf_find(b);
        if (a == b) return;
        if (a > b) { int t = a; a = b; b = t; }
        int old = atomicCAS(&g_label[b], b, a);
        if (old == b) return;
        b = old;
    }
}

// ---------------------------------------------------------------------------
// K4: tile-local CCL, ballot-run style (32x32 tile, 1 warp per row).
// Horizontal runs resolved by ballot (labels = run start, no atomics).
// Vertical merges: ONE union per distinct (run, up-run) contact pair.
__global__ __launch_bounds__(1024) void k_local() {
    __shared__ int lp[1024];
    __shared__ unsigned int rowbits[32];

    int lx = threadIdx.x, ly = threadIdx.y;
    int l  = ly * 32 + lx;
    int x  = blockIdx.x * 32 + lx;
    int y  = blockIdx.y * 32 + ly;
    int b  = blockIdx.z;
    int gi = b * NPIX + y * W + x;

    bool w = (g_ws[gi] & 1);
    unsigned bits = __ballot_sync(0xFFFFFFFFu, w);
    if (lx == 0) rowbits[ly] = bits;

    // run start within this row (for weak lanes)
    int s = 0;
    if (w) {
        unsigned t = ~bits & ((1u << lx) - 1u);
        s = t ? (32 - __clz(t)) : 0;
    }
    lp[l] = w ? (ly * 32 + s) : l;   // depth <= 1 forest
    __syncthreads();

    if (w && ly > 0) {
        unsigned ub = rowbits[ly - 1];
        bool up   = (ub >> lx) & 1u;
        bool upl  = (lx > 0)  && ((ub >> (lx - 1)) & 1u);
        bool upr  = (lx < 31) && ((ub >> (lx + 1)) & 1u);
        bool curl = (lx > 0)  && ((bits >> (lx - 1)) & 1u);
        bool curr = (lx < 31) && ((bits >> (lx + 1)) & 1u);

        // straight: only at leftmost contact of the (run, up-run) pair
        if (up && (lx == s || !upl)) lunion(lp, l, l - 32);
        // left-diag: needed only if not subsumed by straight contacts
        if (upl && !up && !curl) lunion(lp, l, l - 33);
        // right-diag: mirror
        if (upr && !up && !curr) lunion(lp, l, l - 31);
    }
    __syncthreads();

    if (w) {
        int r  = lfind(lp, l);
        int rx = r & 31, ry = r >> 5;
        g_label[gi] = b * NPIX + (blockIdx.y * 32 + ry) * W + (blockIdx.x * 32 + rx);
    }
}

// ---------------------------------------------------------------------------
// K5: merge weak pairs crossing 32x32 tile boundaries
__global__ __launch_bounds__(256) void k_border() {
    int i = blockIdx.x * blockDim.x + threadIdx.x;
    if (i >= TOT) return;
    if (!(g_ws[i] & 1)) return;

    int pi = i % NPIX;
    int x  = pi % W;
    int y  = pi / W;

    bool xe = ((x & 31) == 31);
    bool x0 = ((x & 31) == 0);
    bool ye = ((y & 31) == 31);

    if (x < W - 1 && xe && (g_ws[i + 1] & 1)) uf_union(i, i + 1);
    if (y < H - 1) {
        if (ye                       && (g_ws[i + W]     & 1)) uf_union(i, i + W);
        if (x > 0     && (ye || x0)  && (g_ws[i + W - 1] & 1)) uf_union(i, i + W - 1);
        if (x < W - 1 && (ye || xe)  && (g_ws[i + W + 1] & 1)) uf_union(i, i + W + 1);
    }
}

// ---------------------------------------------------------------------------
// K6: flatten weak labels (find from tile root) + mark strong components
__global__ __launch_bounds__(256) void k_flatmark() {
    int i = blockIdx.x * blockDim.x + threadIdx.x;
    if (i >= TOT) return;
    unsigned char ws = g_ws[i];
    if (ws & 1) {
        int r = uf_find_ro(g_label[i]);
        g_label[i] = r;
        if (ws & 2) g_rootflag[r] = 1;
    }
}

// ---------------------------------------------------------------------------
// K7: output = 50 * (edge - threshold)
__global__ __launch_bounds__(256) void k_out(float* __restrict__ out,
                                             const float* __restrict__ thrp) {
    int i = blockIdx.x * blockDim.x + threadIdx.x;
    if (i >= TOT) return;
    float thr = __ldg(thrp);
    float e = 0.0f;
    if (g_ws[i] & 1) {
        if (g_rootflag[g_label[i]]) e = 1.0f;
    }
    out[i] = __fmul_rn(50.0f, __fadd_rn(e, -thr));
}

// ---------------------------------------------------------------------------
extern "C" void kernel_launch(void* const* d_in, const int* in_sizes, int n_in,
                              void* d_out, int out_size) {
    const float* x     = (const float*)d_in[0];
    const float* thr   = (const float*)d_in[1];
    const float* low   = (const float*)d_in[2];
    const float* high  = (const float*)d_in[3];
    float*       out   = (float*)d_out;

    dim3 blkN(32, 8);
    dim3 grdN(W / 32, H / 8, BATCH);    // stencils
    dim3 blk32(32, 32);
    dim3 grd32(W / 32, H / 32, BATCH);  // local CCL

    k_init<<<(TOT / 16 + 255) / 256, 256>>>();
    k_blur<<<grdN, blkN>>>(x);
    k_sobel<<<grdN, blkN>>>();
    k_nms<<<grdN, blkN>>>(low, high);
    k_local<<<grd32, blk32>>>();
    k_border<<<(TOT + 255) / 256, 256>>>();
    k_flatmark<<<(TOT + 255) / 256, 256>>>();
    k_out<<<(TOT + 255) / 256, 256>>>(out, thr);
}

// round 15
// speedup vs baseline: 1.2582x; 1.0077x over previous
#include <cuda_runtime.h>
#include <math.h>

// Canny: blur -> sobel(+max) -> NMS -> hierarchical CCL (ballot-run local UF,
// border merge, flatten/mark) -> output.
// Conv numerics: REVERSED row-major sequential FFMA (bit-match proven R10).
// Sobel direction: tan-comparison fast path, atan2f fallback in guard band.
// NMS: division-free fast path via monotonicity, exact divides in guard band.

#define BATCH 16
#define H 1024
#define W 1024
#define NPIX (H * W)
#define TOT (BATCH * NPIX)

__device__ float         g_blur[TOT];
__device__ float         g_mag[TOT];
__device__ unsigned char g_dir[TOT];
__device__ unsigned char g_ws[TOT];       // bit0 = weak, bit1 = strong
__device__ int           g_label[TOT];    // union-find parent (weak only)
__device__ unsigned char g_rootflag[TOT]; // component-has-strong flag (by root)
__device__ int           g_maxi[BATCH];   // per-image max(mag) as int bits
__device__ float         g_w25[25];       // numpy-bit-exact gaussian weights

// ---------------------------------------------------------------------------
// K0: zero rootflag + maxi + (thread 0) numpy-bit-exact gaussian weights
__global__ void k_init() {
    int i = blockIdx.x * blockDim.x + threadIdx.x;
    if (i < TOT / 16) {
        reinterpret_cast<uint4*>(g_rootflag)[i] = make_uint4(0u, 0u, 0u, 0u);
    }
    if (i < BATCH) g_maxi[i] = 0;
    if (blockIdx.x == 0 && threadIdx.x == 0) {
        float gf[5];
#pragma unroll
        for (int t = 0; t < 5; t++) {
            double ax = (double)(t - 2);
            gf[t] = (float)exp(-0.5 * ax * ax);
        }
        float p[25];
#pragma unroll
        for (int r = 0; r < 5; r++)
#pragma unroll
            for (int c = 0; c < 5; c++)
                p[r * 5 + c] = __fmul_rn(gf[r], gf[c]);
        float acc8[8];
#pragma unroll
        for (int j = 0; j < 8; j++) acc8[j] = p[j];
#pragma unroll
        for (int j = 0; j < 8; j++) acc8[j] = __fadd_rn(acc8[j], p[8 + j]);
#pragma unroll
        for (int j = 0; j < 8; j++) acc8[j] = __fadd_rn(acc8[j], p[16 + j]);
        float s01 = __fadd_rn(acc8[0], acc8[1]);
        float s23 = __fadd_rn(acc8[2], acc8[3]);
        float s45 = __fadd_rn(acc8[4], acc8[5]);
        float s67 = __fadd_rn(acc8[6], acc8[7]);
        float res = __fadd_rn(__fadd_rn(s01, s23), __fadd_rn(s45, s67));
        res = __fadd_rn(res, p[24]);
#pragma unroll
        for (int k = 0; k < 25; k++) g_w25[k] = __fdiv_rn(p[k], res);
    }
}

// ---------------------------------------------------------------------------
// K1: 5x5 Gaussian blur, REVERSED row-major FFMA (bit-matches reference)
__global__ __launch_bounds__(256) void k_blur(const float* __restrict__ x) {
    int px = blockIdx.x * 32 + threadIdx.x;
    int py = blockIdx.y * 8 + threadIdx.y;
    int b  = blockIdx.z;
    const float* __restrict__ img = x + ((size_t)b * 3 + 1) * NPIX;

    float w[25];
#pragma unroll
    for (int k = 0; k < 25; k++) w[k] = g_w25[k];

    float acc = 0.0f;
#pragma unroll
    for (int ky = 4; ky >= 0; ky--) {
        int sy = py + ky - 2;
        bool yok = (sy >= 0 && sy < H);
#pragma unroll
        for (int kx = 4; kx >= 0; kx--) {
            int sx = px + kx - 2;
            float v = (yok && sx >= 0 && sx < W) ? __ldg(img + sy * W + sx) : 0.0f;
            acc = __fmaf_rn(w[ky * 5 + kx], v, acc);
        }
    }
    g_blur[(size_t)b * NPIX + py * W + px] = acc;
}

// ---------------------------------------------------------------------------
// Slow-path direction (exact previous semantics: atan2f + CR rescue + fmod)
__device__ __noinline__ unsigned char direction_slow(float gx, float gy) {
    float deg = __fmul_rn(atan2f(gy, gx), 57.29577951308232f);
    float r = fmodf(deg, 180.0f);
    if (r < 0.0f) r = __fadd_rn(r, 180.0f);

    float d0 = fabsf(r - 22.5f);
    float d1 = fabsf(r - 67.5f);
    float d2 = fabsf(r - 112.5f);
    float d3 = fabsf(r - 157.5f);
    float dmin = fminf(fminf(d0, d1), fminf(d2, d3));
    if (dmin < 2e-4f) {
        float at = (float)atan2((double)gy, (double)gx);
        deg = __fmul_rn(at, 57.29577951308232f);
        r = fmodf(deg, 180.0f);
        if (r < 0.0f) r = __fadd_rn(r, 180.0f);
    }

    if (r < 22.5f || r >= 157.5f) return 0;
    else if (r < 67.5f)           return 1;
    else if (r < 112.5f)          return 2;
    else                          return 3;
}

// Fast direction: tan comparisons; guard band (1e-4 rel >> atan2f 3-ulp error)
// falls back to slow path, so classification is bit-identical.
__device__ __forceinline__ unsigned char direction_of(float gx, float gy) {
    float ax = fabsf(gx), ay = fabsf(gy);
    float b1 = __fmul_rn(0.41421356237309503f, ax);  // tan(22.5)
    float b2 = __fmul_rn(2.414213562373095f,  ax);   // tan(67.5)
    float e1 = 1e-4f * (ay + b1);
    float e2 = 1e-4f * (ay + b2);
    if (fabsf(ay - b1) <= e1 || fabsf(ay - b2) <= e2)
        return direction_slow(gx, gy);
    if (ay < b1) return 0;
    if (ay > b2) return 2;
    bool same = ((__float_as_int(gx) ^ __float_as_int(gy)) >= 0);
    return same ? 1 : 3;
}

// ---------------------------------------------------------------------------
// K2: Sobel (reversed row-major FFMA) -> mag/dir + per-image max (1 atomic/blk)
__global__ __launch_bounds__(256) void k_sobel() {
    int x = blockIdx.x * 32 + threadIdx.x;
    int y = blockIdx.y * 8 + threadIdx.y;
    int b = blockIdx.z;
    const float* __restrict__ img = g_blur + (size_t)b * NPIX;

    float a[3][3];
#pragma unroll
    for (int i = 0; i < 3; i++) {
#pragma unroll
        for (int j = 0; j < 3; j++) {
            int yy = y + i - 1, xx = x + j - 1;
            a[i][j] = (yy >= 0 && yy < H && xx >= 0 && xx < W) ? img[yy * W + xx] : 0.0f;
        }
    }
    float gx = 0.0f;
    gx = __fmaf_rn( 1.0f, a[2][2], gx);
    gx = __fmaf_rn(-1.0f, a[2][0], gx);
    gx = __fmaf_rn( 2.0f, a[1][2], gx);
    gx = __fmaf_rn(-2.0f, a[1][0], gx);
    gx = __fmaf_rn( 1.0f, a[0][2], gx);
    gx = __fmaf_rn(-1.0f, a[0][0], gx);

    float gy = 0.0f;
    gy = __fmaf_rn( 1.0f, a[2][2], gy);
    gy = __fmaf_rn( 2.0f, a[2][1], gy);
    gy = __fmaf_rn( 1.0f, a[2][0], gy);
    gy = __fmaf_rn(-1.0f, a[0][2], gy);
    gy = __fmaf_rn(-2.0f, a[0][1], gy);
    gy = __fmaf_rn(-1.0f, a[0][0], gy);

    float m2  = __fadd_rn(__fadd_rn(__fmul_rn(gx, gx), __fmul_rn(gy, gy)), 1e-12f);
    float mag = __fsqrt_rn(m2);

    size_t idx = (size_t)b * NPIX + y * W + x;
    g_mag[idx] = mag;
    g_dir[idx] = direction_of(gx, gy);

    __shared__ float s_red[8];
    int t = threadIdx.y * 32 + threadIdx.x;
    float m = mag;
#pragma unroll
    for (int s = 16; s > 0; s >>= 1)
        m = fmaxf(m, __shfl_xor_sync(0xFFFFFFFFu, m, s));
    if ((t & 31) == 0) s_red[t >> 5] = m;
    __syncthreads();
    if (t < 8) {
        m = s_red[t];
#pragma unroll
        for (int s = 4; s > 0; s >>= 1)
            m = fmaxf(m, __shfl_xor_sync(0xFFu, m, s));
        if (t == 0) atomicMax(&g_maxi[b], __float_as_int(m));
    }
}

// ---------------------------------------------------------------------------
// K3: NMS + double threshold. Division-free fast path:
// CR division by denom>0 is monotone, so (m/denom >= n/denom) == (m >= n)
// except when m < n within ~1 ulp (quotients round equal) -> exact divide.
__global__ __launch_bounds__(256) void k_nms(const float* __restrict__ lowp,
                                             const float* __restrict__ highp) {
    int x = blockIdx.x * 32 + threadIdx.x;
    int y = blockIdx.y * 8 + threadIdx.y;
    int b = blockIdx.z;
    const float* __restrict__ mg = g_mag + (size_t)b * NPIX;

    float denom = __fadd_rn(__int_as_float(g_maxi[b]), 1e-12f);
    float low  = __ldg(lowp);
    float high = __ldg(highp);

    int   pi = y * W + x;
    size_t idx = (size_t)b * NPIX + pi;
    float m = __ldg(mg + pi);
    int   d = g_dir[idx];

    float n1, n2;
    if (x >= 1 && x < W - 1 && y >= 1 && y < H - 1) {
        const float* p = mg + pi;
        if (d == 0)      { n1 = __ldg(p + 1);     n2 = __ldg(p - 1);     }
        else if (d == 1) { n1 = __ldg(p - W + 1); n2 = __ldg(p + W - 1); }
        else if (d == 2) { n1 = __ldg(p - W);     n2 = __ldg(p + W);     }
        else             { n1 = __ldg(p - W - 1); n2 = __ldg(p + W + 1); }
    } else {
        auto nb = [&](int yy, int xx) -> float {
            return (yy >= 0 && yy < H && xx >= 0 && xx < W) ? __ldg(mg + yy * W + xx) : 0.0f;
        };
        if (d == 0)      { n1 = nb(y,     x + 1); n2 = nb(y,     x - 1); }
        else if (d == 1) { n1 = nb(y - 1, x + 1); n2 = nb(y + 1, x - 1); }
        else if (d == 2) { n1 = nb(y - 1, x);     n2 = nb(y + 1, x);     }
        else             { n1 = nb(y - 1, x - 1); n2 = nb(y + 1, x + 1); }
    }

    bool ge1, ge2;
    if (m >= n1) ge1 = true;
    else if (m < __fmul_rn(n1, 0.999999f)) ge1 = false;
    else ge1 = (__fdiv_rn(m, denom) >= __fdiv_rn(n1, denom));

    if (m >= n2) ge2 = true;
    else if (m < __fmul_rn(n2, 0.999999f)) ge2 = false;
    else ge2 = (__fdiv_rn(m, denom) >= __fdiv_rn(n2, denom));

    unsigned char ws = 0;
    if (ge1 && ge2) {
        float tl = __fmul_rn(low,  denom);
        float th = __fmul_rn(high, denom);
        bool weak, strong;
        if      (m > __fmul_rn(tl, 1.000002f)) weak = true;
        else if (m < __fmul_rn(tl, 0.999998f)) weak = false;
        else weak = (__fdiv_rn(m, denom) >= low);
        if      (m > __fmul_rn(th, 1.000002f)) strong = true;
        else if (m < __fmul_rn(th, 0.999998f)) strong = false;
        else strong = (__fdiv_rn(m, denom) >= high);
        if (weak)   ws |= 1;
        if (strong) ws |= 2;
    } else {
        if (0.0f >= low)  ws |= 1;   // nms == 0 case (exact reference logic)
        if (0.0f >= high) ws |= 2;
    }

    g_ws[idx] = ws;
}

// ---------------------------------------------------------------------------
// Shared-memory union-find (tile-local, min-root)
__device__ __forceinline__ int lfind(int* lp, int i) {
    volatile int* L = lp;
    while (true) {
        int p = L[i];
        if (p == i) return i;
        int gp = L[p];
        if (gp == p) return p;
        lp[i] = gp;
        i = gp;
    }
}
__device__ __forceinline__ void lunion(int* lp, int a, int b) {
    while (true) {
        a = lfind(lp, a);
        b = lfind(lp, b);
        if (a == b) return;
        if (a > b) { int t = a; a = b; b = t; }
        int old = atomicCAS(&lp[b], b, a);
        if (old == b) return;
        b = old;
    }
}

// Global union-find (min-root)
__device__ __forceinline__ int uf_find(int i) {
    volatile int* L = g_label;
    while (true) {
        int p = L[i];
        if (p == i) return i;
        int gp = L[p];
        if (gp == p) return p;
        g_label[i] = gp;
        i = gp;
    }
}
__device__ __forceinline__ int uf_find_ro(int i) {
    volatile int* L = g_label;
    while (true) {
        int p = L[i];
        if (p == i) return i;
        i = p;
    }
}
__device__ __forceinline__ void uf_union(int a, int b) {
    while (true) {
        a = uf_find(a);
        b = uf_find(b);
        if (a == b) return;
        if (a > b) { int t = a; a = b; b = t; }
        int old = atomicCAS(&g_label[b], b, a);
        if (old == b) return;
        b = old;
    }
}

// ---------------------------------------------------------------------------
// K4: tile-local CCL, ballot-run style (32x32 tile, 1 warp per row).
__global__ __launch_bounds__(1024) void k_local() {
    __shared__ int lp[1024];
    __shared__ unsigned int rowbits[32];

    int lx = threadIdx.x, ly = threadIdx.y;
    int l  = ly * 32 + lx;
    int x  = blockIdx.x * 32 + lx;
    int y  = blockIdx.y * 32 + ly;
    int b  = blockIdx.z;
    int gi = b * NPIX + y * W + x;

    bool w = (g_ws[gi] & 1);
    unsigned bits = __ballot_sync(0xFFFFFFFFu, w);
    if (lx == 0) rowbits[ly] = bits;

    int s = 0;
    if (w) {
        unsigned t = ~bits & ((1u << lx) - 1u);
        s = t ? (32 - __clz(t)) : 0;
    }
    lp[l] = w ? (ly * 32 + s) : l;
    __syncthreads();

    if (w && ly > 0) {
        unsigned ub = rowbits[ly - 1];
        bool up   = (ub >> lx) & 1u;
        bool upl  = (lx > 0)  && ((ub >> (lx - 1)) & 1u);
        bool upr  = (lx < 31) && ((ub >> (lx + 1)) & 1u);
        bool curl = (lx > 0)  && ((bits >> (lx - 1)) & 1u);
        bool curr = (lx < 31) && ((bits >> (lx + 1)) & 1u);

        if (up && (lx == s || !upl)) lunion(lp, l, l - 32);
        if (upl && !up && !curl) lunion(lp, l, l - 33);
        if (upr && !up && !curr) lunion(lp, l, l - 31);
    }
    __syncthreads();

    if (w) {
        int r  = lfind(lp, l);
        int rx = r & 31, ry = r >> 5;
        g_label[gi] = b * NPIX + (blockIdx.y * 32 + ry) * W + (blockIdx.x * 32 + rx);
    }
}

// ---------------------------------------------------------------------------
// K5: merge weak pairs crossing 32x32 tile boundaries
__global__ __launch_bounds__(256) void k_border() {
    int i = blockIdx.x * blockDim.x + threadIdx.x;
    if (i >= TOT) return;
    if (!(g_ws[i] & 1)) return;

    int pi = i % NPIX;
    int x  = pi % W;
    int y  = pi / W;

    bool xe = ((x & 31) == 31);
    bool x0 = ((x & 31) == 0);
    bool ye = ((y & 31) == 31);

    if (x < W - 1 && xe && (g_ws[i + 1] & 1)) uf_union(i, i + 1);
    if (y < H - 1) {
        if (ye                       && (g_ws[i + W]     & 1)) uf_union(i, i + W);
        if (x > 0     && (ye || x0)  && (g_ws[i + W - 1] & 1)) uf_union(i, i + W - 1);
        if (x < W - 1 && (ye || xe)  && (g_ws[i + W + 1] & 1)) uf_union(i, i + W + 1);
    }
}

// ---------------------------------------------------------------------------
// K6: flatten weak labels (find from tile root) + mark strong components
__global__ __launch_bounds__(256) void k_flatmark() {
    int i = blockIdx.x * blockDim.x + threadIdx.x;
    if (i >= TOT) return;
    unsigned char ws = g_ws[i];
    if (ws & 1) {
        int r = uf_find_ro(g_label[i]);
        g_label[i] = r;
        if (ws & 2) g_rootflag[r] = 1;
    }
}

// ---------------------------------------------------------------------------
// K7: output = 50 * (edge - threshold)
__global__ __launch_bounds__(256) void k_out(float* __restrict__ out,
                                             const float* __restrict__ thrp) {
    int i = blockIdx.x * blockDim.x + threadIdx.x;
    if (i >= TOT) return;
    float thr = __ldg(thrp);
    float e = 0.0f;
    if (g_ws[i] & 1) {
        if (g_rootflag[g_label[i]]) e = 1.0f;
    }
    out[i] = __fmul_rn(50.0f, __fadd_rn(e, -thr));
}

// ---------------------------------------------------------------------------
extern "C" void kernel_launch(void* const* d_in, const int* in_sizes, int n_in,
                              void* d_out, int out_size) {
    const float* x     = (const float*)d_in[0];
    const float* thr   = (const float*)d_in[1];
    const float* low   = (const float*)d_in[2];
    const float* high  = (const float*)d_in[3];
    float*       out   = (float*)d_out;

    dim3 blkN(32, 8);
    dim3 grdN(W / 32, H / 8, BATCH);    // stencils
    dim3 blk32(32, 32);
    dim3 grd32(W / 32, H / 32, BATCH);  // local CCL

    k_init<<<(TOT / 16 + 255) / 256, 256>>>();
    k_blur<<<grdN, blkN>>>(x);
    k_sobel<<<grdN, blkN>>>();
    k_nms<<<grdN, blkN>>>(low, high);
    k_local<<<grd32, blk32>>>();
    k_border<<<(TOT + 255) / 256, 256>>>();
    k_flatmark<<<(TOT + 255) / 256, 256>>>();
    k_out<<<(TOT + 255) / 256, 256>>>(out, thr);
}

// round 17
// speedup vs baseline: 1.5045x; 1.1957x over previous
#include <cuda_runtime.h>
#include <math.h>

// Canny: blur -> sobel(+max) -> NMS -> CCL (ballot-run local UF, border merge,
// strong-mark) -> output(with inline find).
// Conv numerics: REVERSED row-major sequential FFMA (bit-match proven R10).
// Stencils process 4 pixels/thread (interior fast path) — per-pixel op order
// unchanged, so results stay bit-identical.

#define BATCH 16
#define H 1024
#define W 1024
#define NPIX (H * W)
#define TOT (BATCH * NPIX)

__device__ float         g_blur[TOT];
__device__ float         g_mag[TOT];
__device__ unsigned char g_dir[TOT];
__device__ unsigned char g_ws[TOT];       // bit0 = weak, bit1 = strong
__device__ int           g_label[TOT];    // union-find parent (weak only)
__device__ unsigned char g_rootflag[TOT]; // component-has-strong flag (by root)
__device__ int           g_maxi[BATCH];   // per-image max(mag) as int bits
__device__ float         g_w25[25];       // numpy-bit-exact gaussian weights

// ---------------------------------------------------------------------------
__global__ void k_init() {
    int i = blockIdx.x * blockDim.x + threadIdx.x;
    if (i < TOT / 16) {
        reinterpret_cast<uint4*>(g_rootflag)[i] = make_uint4(0u, 0u, 0u, 0u);
    }
    if (i < BATCH) g_maxi[i] = 0;
    if (blockIdx.x == 0 && threadIdx.x == 0) {
        float gf[5];
#pragma unroll
        for (int t = 0; t < 5; t++) {
            double ax = (double)(t - 2);
            gf[t] = (float)exp(-0.5 * ax * ax);
        }
        float p[25];
#pragma unroll
        for (int r = 0; r < 5; r++)
#pragma unroll
            for (int c = 0; c < 5; c++)
                p[r * 5 + c] = __fmul_rn(gf[r], gf[c]);
        float acc8[8];
#pragma unroll
        for (int j = 0; j < 8; j++) acc8[j] = p[j];
#pragma unroll
        for (int j = 0; j < 8; j++) acc8[j] = __fadd_rn(acc8[j], p[8 + j]);
#pragma unroll
        for (int j = 0; j < 8; j++) acc8[j] = __fadd_rn(acc8[j], p[16 + j]);
        float s01 = __fadd_rn(acc8[0], acc8[1]);
        float s23 = __fadd_rn(acc8[2], acc8[3]);
        float s45 = __fadd_rn(acc8[4], acc8[5]);
        float s67 = __fadd_rn(acc8[6], acc8[7]);
        float res = __fadd_rn(__fadd_rn(s01, s23), __fadd_rn(s45, s67));
        res = __fadd_rn(res, p[24]);
#pragma unroll
        for (int k = 0; k < 25; k++) g_w25[k] = __fdiv_rn(p[k], res);
    }
}

// ---------------------------------------------------------------------------
// K1: 5x5 blur, 4 pixels/thread, REVERSED row-major FFMA per pixel.
__global__ __launch_bounds__(256) void k_blur(const float* __restrict__ xin) {
    int px0 = (blockIdx.x * 32 + threadIdx.x) * 4;   // grid.x = W/128
    int py  = blockIdx.y * 8 + threadIdx.y;
    int b   = blockIdx.z;
    const float* __restrict__ img = xin + ((size_t)b * 3 + 1) * NPIX;

    float w[25];
#pragma unroll
    for (int k = 0; k < 25; k++) w[k] = g_w25[k];

    float acc[4] = {0.0f, 0.0f, 0.0f, 0.0f};

    if (px0 >= 4 && px0 + 5 < W && py >= 2 && py < H - 2) {
        // interior: shared 5x8 neighborhood
#pragma unroll
        for (int ky = 4; ky >= 0; ky--) {
            const float* row = img + (py + ky - 2) * W + px0 - 2;
            float v[8];
#pragma unroll
            for (int j = 0; j < 8; j++) v[j] = __ldg(row + j);
#pragma unroll
            for (int kx = 4; kx >= 0; kx--) {
                float wv = w[ky * 5 + kx];
                acc[0] = __fmaf_rn(wv, v[kx],     acc[0]);
                acc[1] = __fmaf_rn(wv, v[kx + 1], acc[1]);
                acc[2] = __fmaf_rn(wv, v[kx + 2], acc[2]);
                acc[3] = __fmaf_rn(wv, v[kx + 3], acc[3]);
            }
        }
    } else {
#pragma unroll
        for (int q = 0; q < 4; q++) {
            int px = px0 + q;
            float a = 0.0f;
#pragma unroll
            for (int ky = 4; ky >= 0; ky--) {
                int sy = py + ky - 2;
                bool yok = (sy >= 0 && sy < H);
#pragma unroll
                for (int kx = 4; kx >= 0; kx--) {
                    int sx = px + kx - 2;
                    float v = (yok && sx >= 0 && sx < W) ? __ldg(img + sy * W + sx) : 0.0f;
                    a = __fmaf_rn(w[ky * 5 + kx], v, a);
                }
            }
            acc[q] = a;
        }
    }
    *reinterpret_cast<float4*>(g_blur + (size_t)b * NPIX + py * W + px0) =
        make_float4(acc[0], acc[1], acc[2], acc[3]);
}

// ---------------------------------------------------------------------------
__device__ __noinline__ unsigned char direction_slow(float gx, float gy) {
    float deg = __fmul_rn(atan2f(gy, gx), 57.29577951308232f);
    float r = fmodf(deg, 180.0f);
    if (r < 0.0f) r = __fadd_rn(r, 180.0f);
    float d0 = fabsf(r - 22.5f);
    float d1 = fabsf(r - 67.5f);
    float d2 = fabsf(r - 112.5f);
    float d3 = fabsf(r - 157.5f);
    float dmin = fminf(fminf(d0, d1), fminf(d2, d3));
    if (dmin < 2e-4f) {
        float at = (float)atan2((double)gy, (double)gx);
        deg = __fmul_rn(at, 57.29577951308232f);
        r = fmodf(deg, 180.0f);
        if (r < 0.0f) r = __fadd_rn(r, 180.0f);
    }
    if (r < 22.5f || r >= 157.5f) return 0;
    else if (r < 67.5f)           return 1;
    else if (r < 112.5f)          return 2;
    else                          return 3;
}

__device__ __forceinline__ unsigned char direction_of(float gx, float gy) {
    float ax = fabsf(gx), ay = fabsf(gy);
    float b1 = __fmul_rn(0.41421356237309503f, ax);
    float b2 = __fmul_rn(2.414213562373095f,  ax);
    float e1 = 1e-4f * (ay + b1);
    float e2 = 1e-4f * (ay + b2);
    if (fabsf(ay - b1) <= e1 || fabsf(ay - b2) <= e2)
        return direction_slow(gx, gy);
    if (ay < b1) return 0;
    if (ay > b2) return 2;
    bool same = ((__float_as_int(gx) ^ __float_as_int(gy)) >= 0);
    return same ? 1 : 3;
}

// ---------------------------------------------------------------------------
// K2: Sobel, 4 pixels/thread -> mag/dir + per-image max
__global__ __launch_bounds__(256) void k_sobel() {
    int px0 = (blockIdx.x * 32 + threadIdx.x) * 4;
    int py  = blockIdx.y * 8 + threadIdx.y;
    int b   = blockIdx.z;
    const float* __restrict__ img = g_blur + (size_t)b * NPIX;

    float v[3][6];
    if (px0 >= 4 && px0 + 4 < W && py >= 1 && py < H - 1) {
#pragma unroll
        for (int i = 0; i < 3; i++) {
            const float* row = img + (py + i - 1) * W + px0 - 1;
#pragma unroll
            for (int j = 0; j < 6; j++) v[i][j] = __ldg(row + j);
        }
    } else {
#pragma unroll
        for (int i = 0; i < 3; i++) {
            int yy = py + i - 1;
            bool yok = (yy >= 0 && yy < H);
#pragma unroll
            for (int j = 0; j < 6; j++) {
                int xx = px0 - 1 + j;
                v[i][j] = (yok && xx >= 0 && xx < W) ? __ldg(img + yy * W + xx) : 0.0f;
            }
        }
    }

    float mags[4];
    unsigned char dirs[4];
    float mwarp = 0.0f;
#pragma unroll
    for (int q = 0; q < 4; q++) {
        float gx = 0.0f;
        gx = __fmaf_rn( 1.0f, v[2][q + 2], gx);
        gx = __fmaf_rn(-1.0f, v[2][q],     gx);
        gx = __fmaf_rn( 2.0f, v[1][q + 2], gx);
        gx = __fmaf_rn(-2.0f, v[1][q],     gx);
        gx = __fmaf_rn( 1.0f, v[0][q + 2], gx);
        gx = __fmaf_rn(-1.0f, v[0][q],     gx);

        float gy = 0.0f;
        gy = __fmaf_rn( 1.0f, v[2][q + 2], gy);
        gy = __fmaf_rn( 2.0f, v[2][q + 1], gy);
        gy = __fmaf_rn( 1.0f, v[2][q],     gy);
        gy = __fmaf_rn(-1.0f, v[0][q + 2], gy);
        gy = __fmaf_rn(-2.0f, v[0][q + 1], gy);
        gy = __fmaf_rn(-1.0f, v[0][q],     gy);

        float m2 = __fadd_rn(__fadd_rn(__fmul_rn(gx, gx), __fmul_rn(gy, gy)), 1e-12f);
        mags[q] = __fsqrt_rn(m2);
        dirs[q] = direction_of(gx, gy);
        mwarp = fmaxf(mwarp, mags[q]);
    }

    size_t base = (size_t)b * NPIX + py * W + px0;
    *reinterpret_cast<float4*>(g_mag + base) = make_float4(mags[0], mags[1], mags[2], mags[3]);
    *reinterpret_cast<uchar4*>(g_dir + base) = make_uchar4(dirs[0], dirs[1], dirs[2], dirs[3]);

    __shared__ float s_red[8];
    int t = threadIdx.y * 32 + threadIdx.x;
#pragma unroll
    for (int s = 16; s > 0; s >>= 1)
        mwarp = fmaxf(mwarp, __shfl_xor_sync(0xFFFFFFFFu, mwarp, s));
    if ((t & 31) == 0) s_red[t >> 5] = mwarp;
    __syncthreads();
    if (t < 8) {
        float m = s_red[t];
#pragma unroll
        for (int s = 4; s > 0; s >>= 1)
            m = fmaxf(m, __shfl_xor_sync(0xFFu, m, s));
        if (t == 0) atomicMax(&g_maxi[b], __float_as_int(m));
    }
}

// ---------------------------------------------------------------------------
// K3: NMS + double threshold (division-free fast path, exact divide in band)
__global__ __launch_bounds__(256) void k_nms(const float* __restrict__ lowp,
                                             const float* __restrict__ highp) {
    int x = blockIdx.x * 32 + threadIdx.x;
    int y = blockIdx.y * 8 + threadIdx.y;
    int b = blockIdx.z;
    const float* __restrict__ mg = g_mag + (size_t)b * NPIX;

    float denom = __fadd_rn(__int_as_float(g_maxi[b]), 1e-12f);
    float low  = __ldg(lowp);
    float high = __ldg(highp);

    int   pi = y * W + x;
    size_t idx = (size_t)b * NPIX + pi;
    float m = __ldg(mg + pi);
    int   d = g_dir[idx];

    float n1, n2;
    if (x >= 1 && x < W - 1 && y >= 1 && y < H - 1) {
        const float* p = mg + pi;
        if (d == 0)      { n1 = __ldg(p + 1);     n2 = __ldg(p - 1);     }
        else if (d == 1) { n1 = __ldg(p - W + 1); n2 = __ldg(p + W - 1); }
        else if (d == 2) { n1 = __ldg(p - W);     n2 = __ldg(p + W);     }
        else             { n1 = __ldg(p - W - 1); n2 = __ldg(p + W + 1); }
    } else {
        auto nb = [&](int yy, int xx) -> float {
            return (yy >= 0 && yy < H && xx >= 0 && xx < W) ? __ldg(mg + yy * W + xx) : 0.0f;
        };
        if (d == 0)      { n1 = nb(y,     x + 1); n2 = nb(y,     x - 1); }
        else if (d == 1) { n1 = nb(y - 1, x + 1); n2 = nb(y + 1, x - 1); }
        else if (d == 2) { n1 = nb(y - 1, x);     n2 = nb(y + 1, x);     }
        else             { n1 = nb(y - 1, x - 1); n2 = nb(y + 1, x + 1); }
    }

    bool ge1, ge2;
    if (m >= n1) ge1 = true;
    else if (m < __fmul_rn(n1, 0.999999f)) ge1 = false;
    else ge1 = (__fdiv_rn(m, denom) >= __fdiv_rn(n1, denom));

    if (m >= n2) ge2 = true;
    else if (m < __fmul_rn(n2, 0.999999f)) ge2 = false;
    else ge2 = (__fdiv_rn(m, denom) >= __fdiv_rn(n2, denom));

    unsigned char ws = 0;
    if (ge1 && ge2) {
        float tl = __fmul_rn(low,  denom);
        float th = __fmul_rn(high, denom);
        bool weak, strong;
        if      (m > __fmul_rn(tl, 1.000002f)) weak = true;
        else if (m < __fmul_rn(tl, 0.999998f)) weak = false;
        else weak = (__fdiv_rn(m, denom) >= low);
        if      (m > __fmul_rn(th, 1.000002f)) strong = true;
        else if (m < __fmul_rn(th, 0.999998f)) strong = false;
        else strong = (__fdiv_rn(m, denom) >= high);
        if (weak)   ws |= 1;
        if (strong) ws |= 2;
    } else {
        if (0.0f >= low)  ws |= 1;
        if (0.0f >= high) ws |= 2;
    }

    g_ws[idx] = ws;
}

// ---------------------------------------------------------------------------
__device__ __forceinline__ int lfind(int* lp, int i) {
    volatile int* L = lp;
    while (true) {
        int p = L[i];
        if (p == i) return i;
        int gp = L[p];
        if (gp == p) return p;
        lp[i] = gp;
        i = gp;
    }
}
__device__ __forceinline__ void lunion(int* lp, int a, int b) {
    while (true) {
        a = lfind(lp, a);
        b = lfind(lp, b);
        if (a == b) return;
        if (a > b) { int t = a; a = b; b = t; }
        int old = atomicCAS(&lp[b], b, a);
        if (old == b) return;
        b = old;
    }
}
__device__ __forceinline__ int uf_find(int i) {
    volatile int* L = g_label;
    while (true) {
        int p = L[i];
        if (p == i) return i;
        int gp = L[p];
        if (gp == p) return p;
        g_label[i] = gp;
        i = gp;
    }
}
__device__ __forceinline__ int uf_find_ro(int i) {
    volatile int* L = g_label;
    while (true) {
        int p = L[i];
        if (p == i) return i;
        i = p;
    }
}
__device__ __forceinline__ void uf_union(int a, int b) {
    while (true) {
        a = uf_find(a);
        b = uf_find(b);
        if (a == b) return;
        if (a > b) { int t = a; a = b; b = t; }
        int old = atomicCAS(&g_label[b], b, a);
        if (old == b) return;
        b = old;
    }
}

// ---------------------------------------------------------------------------
// K4: tile-local CCL, ballot-run style (32x32 tile, 1 warp per row)
__global__ __launch_bounds__(1024) void k_local() {
    __shared__ int lp[1024];
    __shared__ unsigned int rowbits[32];

    int lx = threadIdx.x, ly = threadIdx.y;
    int l  = ly * 32 + lx;
    int x  = blockIdx.x * 32 + lx;
    int y  = blockIdx.y * 32 + ly;
    int b  = blockIdx.z;
    int gi = b * NPIX + y * W + x;

    bool w = (g_ws[gi] & 1);
    unsigned bits = __ballot_sync(0xFFFFFFFFu, w);
    if (lx == 0) rowbits[ly] = bits;

    int s = 0;
    if (w) {
        unsigned t = ~bits & ((1u << lx) - 1u);
        s = t ? (32 - __clz(t)) : 0;
    }
    lp[l] = w ? (ly * 32 + s) : l;
    __syncthreads();

    if (w && ly > 0) {
        unsigned ub = rowbits[ly - 1];
        bool up   = (ub >> lx) & 1u;
        bool upl  = (lx > 0)  && ((ub >> (lx - 1)) & 1u);
        bool upr  = (lx < 31) && ((ub >> (lx + 1)) & 1u);
        bool curl = (lx > 0)  && ((bits >> (lx - 1)) & 1u);
        bool curr = (lx < 31) && ((bits >> (lx + 1)) & 1u);

        if (up && (lx == s || !upl)) lunion(lp, l, l - 32);
        if (upl && !up && !curl) lunion(lp, l, l - 33);
        if (upr && !up && !curr) lunion(lp, l, l - 31);
    }
    __syncthreads();

    if (w) {
        int r  = lfind(lp, l);
        int rx = r & 31, ry = r >> 5;
        g_label[gi] = b * NPIX + (blockIdx.y * 32 + ry) * W + (blockIdx.x * 32 + rx);
    }
}

// ---------------------------------------------------------------------------
// K5: merge weak pairs crossing 32x32 tile boundaries
__global__ __launch_bounds__(256) void k_border() {
    int i = blockIdx.x * blockDim.x + threadIdx.x;
    if (i >= TOT) return;
    if (!(g_ws[i] & 1)) return;

    int pi = i % NPIX;
    int x  = pi % W;
    int y  = pi / W;

    bool xe = ((x & 31) == 31);
    bool x0 = ((x & 31) == 0);
    bool ye = ((y & 31) == 31);

    if (x < W - 1 && xe && (g_ws[i + 1] & 1)) uf_union(i, i + 1);
    if (y < H - 1) {
        if (ye                       && (g_ws[i + W]     & 1)) uf_union(i, i + W);
        if (x > 0     && (ye || x0)  && (g_ws[i + W - 1] & 1)) uf_union(i, i + W - 1);
        if (x < W - 1 && (ye || xe)  && (g_ws[i + W + 1] & 1)) uf_union(i, i + W + 1);
    }
}

// ---------------------------------------------------------------------------
// K6: mark components containing a strong pixel (strong pixels only)
__global__ __launch_bounds__(256) void k_mark() {
    int i0 = (blockIdx.x * blockDim.x + threadIdx.x) * 4;
    if (i0 >= TOT) return;
    unsigned wsv = *reinterpret_cast<const unsigned*>(g_ws + i0);
    if ((wsv & 0x02020202u) == 0u) return;
#pragma unroll
    for (int q = 0; q < 4; q++) {
        if ((wsv >> (q * 8)) & 2u) {
            g_rootflag[uf_find(g_label[i0 + q])] = 1;
        }
    }
}

// ---------------------------------------------------------------------------
// K7: output = 50 * (edge - threshold); inline read-only find per weak pixel
__global__ __launch_bounds__(256) void k_out(float* __restrict__ out,
                                             const float* __restrict__ thrp) {
    int i0 = (blockIdx.x * blockDim.x + threadIdx.x) * 4;
    if (i0 >= TOT) return;
    float thr = __ldg(thrp);
    float lo = __fmul_rn(50.0f, __fadd_rn(0.0f, -thr));
    float hi = __fmul_rn(50.0f, __fadd_rn(1.0f, -thr));

    unsigned wsv = *reinterpret_cast<const unsigned*>(g_ws + i0);
    float o[4];
#pragma unroll
    for (int q = 0; q < 4; q++) {
        float e = lo;
        if ((wsv >> (q * 8)) & 1u) {
            int r = uf_find_ro(g_label[i0 + q]);
            if (g_rootflag[r]) e = hi;
        }
        o[q] = e;
    }
    *reinterpret_cast<float4*>(out + i0) = make_float4(o[0], o[1], o[2], o[3]);
}

// ---------------------------------------------------------------------------
extern "C" void kernel_launch(void* const* d_in, const int* in_sizes, int n_in,
                              void* d_out, int out_size) {
    const float* x     = (const float*)d_in[0];
    const float* thr   = (const float*)d_in[1];
    const float* low   = (const float*)d_in[2];
    const float* high  = (const float*)d_in[3];
    float*       out   = (float*)d_out;

    dim3 blkV(32, 8);
    dim3 grdV(W / 128, H / 8, BATCH);   // 4-wide stencils
    dim3 grdN(W / 32, H / 8, BATCH);    // scalar NMS
    dim3 blk32(32, 32);
    dim3 grd32(W / 32, H / 32, BATCH);  // local CCL

    k_init<<<(TOT / 16 + 255) / 256, 256>>>();
    k_blur<<<grdV, blkV>>>(x);
    k_sobel<<<grdV, blkV>>>();
    k_nms<<<grdN, blkV>>>(low, high);
    k_local<<<grd32, blk32>>>();
    k_border<<<(TOT + 255) / 256, 256>>>();
    k_mark<<<(TOT / 4 + 255) / 256, 256>>>();
    k_out<<<(TOT / 4 + 255) / 256, 256>>>(out, thr);
}